// round 4
// baseline (speedup 1.0000x reference)
#include <cuda_runtime.h>
#include <cuda_bf16.h>

#define NF   2048
#define NF4  (NF / 4)      // 512 float4 per row
#define P    256           // row chunks
#define EPS  1e-6f

// Scratch (__device__ globals per allocation-free rule)
__device__ __align__(16) float g_ps[P * NF];   // partial sums   [p][c]
__device__ __align__(16) float g_pq[P * NF];   // partial sumsq  [p][c]
__device__ __align__(16) float g_mean[NF];
__device__ __align__(16) float g_istd[NF];

// grid (NF4/256, P), block 256. Thread owns 4 adjacent columns, rows/P rows.
// Atomic-free: coalesced float4 partial stores.
__global__ void reduce_kernel(const float* __restrict__ x, int rows) {
    int col4 = blockIdx.x * 256 + threadIdx.x;     // 0..NF4-1
    int p    = blockIdx.y;                          // 0..P-1
    int rpc  = rows / P;                            // 32
    int r0   = p * rpc;

    const float4* xp = reinterpret_cast<const float4*>(x);

    float sx = 0.f, sy = 0.f, sz = 0.f, sw = 0.f;
    float qx = 0.f, qy = 0.f, qz = 0.f, qw = 0.f;

    #pragma unroll 1
    for (int r = 0; r < rpc; r += 4) {
        size_t base = (size_t)(r0 + r) * NF4 + col4;
        float4 v0 = xp[base];
        float4 v1 = xp[base + NF4];
        float4 v2 = xp[base + 2 * NF4];
        float4 v3 = xp[base + 3 * NF4];
        sx += v0.x; sy += v0.y; sz += v0.z; sw += v0.w;
        qx += v0.x * v0.x; qy += v0.y * v0.y; qz += v0.z * v0.z; qw += v0.w * v0.w;
        sx += v1.x; sy += v1.y; sz += v1.z; sw += v1.w;
        qx += v1.x * v1.x; qy += v1.y * v1.y; qz += v1.z * v1.z; qw += v1.w * v1.w;
        sx += v2.x; sy += v2.y; sz += v2.z; sw += v2.w;
        qx += v2.x * v2.x; qy += v2.y * v2.y; qz += v2.z * v2.z; qw += v2.w * v2.w;
        sx += v3.x; sy += v3.y; sz += v3.z; sw += v3.w;
        qx += v3.x * v3.x; qy += v3.y * v3.y; qz += v3.z * v3.z; qw += v3.w * v3.w;
    }

    float4* psp = reinterpret_cast<float4*>(g_ps);
    float4* pqp = reinterpret_cast<float4*>(g_pq);
    size_t o = (size_t)p * NF4 + col4;
    psp[o] = make_float4(sx, sy, sz, sw);
    pqp[o] = make_float4(qx, qy, qz, qw);
}

// One warp per col4 group (4 columns). Lane sums P/32=8 partials, then
// shfl butterfly.
__global__ void stats_kernel(int rows) {
    int gwarp = (blockIdx.x * blockDim.x + threadIdx.x) >> 5;  // 0..NF4-1
    int lane  = threadIdx.x & 31;
    if (gwarp >= NF4) return;

    const float4* psp = reinterpret_cast<const float4*>(g_ps);
    const float4* pqp = reinterpret_cast<const float4*>(g_pq);

    float4 s = make_float4(0.f, 0.f, 0.f, 0.f);
    float4 q = make_float4(0.f, 0.f, 0.f, 0.f);
    #pragma unroll
    for (int pp = 0; pp < P; pp += 32) {
        float4 a = psp[(size_t)(pp + lane) * NF4 + gwarp];
        float4 b = pqp[(size_t)(pp + lane) * NF4 + gwarp];
        s.x += a.x; s.y += a.y; s.z += a.z; s.w += a.w;
        q.x += b.x; q.y += b.y; q.z += b.z; q.w += b.w;
    }
    #pragma unroll
    for (int off = 16; off > 0; off >>= 1) {
        s.x += __shfl_xor_sync(0xffffffffu, s.x, off);
        s.y += __shfl_xor_sync(0xffffffffu, s.y, off);
        s.z += __shfl_xor_sync(0xffffffffu, s.z, off);
        s.w += __shfl_xor_sync(0xffffffffu, s.w, off);
        q.x += __shfl_xor_sync(0xffffffffu, q.x, off);
        q.y += __shfl_xor_sync(0xffffffffu, q.y, off);
        q.z += __shfl_xor_sync(0xffffffffu, q.z, off);
        q.w += __shfl_xor_sync(0xffffffffu, q.w, off);
    }
    if (lane == 0) {
        float n = (float)rows;
        float inv_n = 1.0f / n;
        float inv_n1 = 1.0f / (n - 1.0f);
        float4 m, is;
        m.x = s.x * inv_n; m.y = s.y * inv_n; m.z = s.z * inv_n; m.w = s.w * inv_n;
        is.x = rsqrtf((q.x - n * m.x * m.x) * inv_n1 + EPS);
        is.y = rsqrtf((q.y - n * m.y * m.y) * inv_n1 + EPS);
        is.z = rsqrtf((q.z - n * m.z * m.z) * inv_n1 + EPS);
        is.w = rsqrtf((q.w - n * m.w * m.w) * inv_n1 + EPS);
        reinterpret_cast<float4*>(g_mean)[gwarp] = m;
        reinterpret_cast<float4*>(g_istd)[gwarp] = is;
    }
}

// Column-aligned normalize: thread strides by NF4 (one row), so all 8 of its
// float4 chunks share the SAME column group -> mean/istd loaded once, MLP=8.
// Block covers 256 contiguous float4 (half a row) x 8 rows.
__global__ void normalize_kernel(const float* __restrict__ x,
                                 float* __restrict__ out, int rows) {
    int half  = blockIdx.x & 1;                    // which half-row
    int strip = blockIdx.x >> 1;                   // 8-row strip index
    int col4  = half * 256 + threadIdx.x;          // 0..NF4-1
    size_t base = (size_t)strip * 8 * NF4 + col4;

    const float4* xp = reinterpret_cast<const float4*>(x);
    float4* op = reinterpret_cast<float4*>(out);

    float4 m = reinterpret_cast<const float4*>(g_mean)[col4];
    float4 s = reinterpret_cast<const float4*>(g_istd)[col4];

    float4 v[8];
    #pragma unroll
    for (int k = 0; k < 8; k++) v[k] = xp[base + (size_t)k * NF4];

    #pragma unroll
    for (int k = 0; k < 8; k++) {
        float4 o;
        o.x = (v[k].x - m.x) * s.x;
        o.y = (v[k].y - m.y) * s.y;
        o.z = (v[k].z - m.z) * s.z;
        o.w = (v[k].w - m.w) * s.w;
        __stcs(&op[base + (size_t)k * NF4], o);
    }
}

extern "C" void kernel_launch(void* const* d_in, const int* in_sizes, int n_in,
                              void* d_out, int out_size) {
    const float* x = (const float*)d_in[0];
    float* out = (float*)d_out;
    int rows = in_sizes[0] / NF;     // 8192

    // 1. atomic-free column reduce into [P][NF] partials (512 CTAs)
    dim3 rgrid(NF4 / 256, P);
    reduce_kernel<<<rgrid, 256>>>(x, rows);

    // 2. stats: one warp per 4 columns
    stats_kernel<<<(NF4 * 32 + 255) / 256, 256>>>(rows);

    // 3. normalize: 8 rows x half-row per block
    int nblocks = (rows / 8) * 2;                  // 2048
    normalize_kernel<<<nblocks, 256>>>(x, out, rows);
}

// round 5
// speedup vs baseline: 1.1424x; 1.1424x over previous
#include <cuda_runtime.h>
#include <cuda_bf16.h>

#define NF    2048
#define NF4   (NF / 4)       // 512 float4 per row
#define P     256            // row chunks == half the grid
#define GRID  512            // 2 col-blocks x P chunks; all co-resident (<=4/SM)
#define EPS   1e-6f

// Scratch (__device__ globals per allocation-free rule)
__device__ __align__(16) float g_ps[P * NF];   // partial sums   [p][c]
__device__ __align__(16) float g_pq[P * NF];   // partial sumsq  [p][c]
__device__ __align__(16) float g_mean[NF];
__device__ __align__(16) float g_istd[NF];

// Grid-barrier counters (zero-init; reset by last CTA each launch so graph
// replays start clean)
__device__ volatile unsigned g_bar1;
__device__ volatile unsigned g_bar2;
__device__ unsigned g_bar3;

__device__ __forceinline__ void grid_barrier(volatile unsigned* bar) {
    __syncthreads();
    __threadfence();
    if (threadIdx.x == 0) {
        atomicAdd((unsigned*)bar, 1u);
        while (*bar < GRID) { }
    }
    __syncthreads();
    __threadfence();
}

__global__ void __launch_bounds__(256, 4)
fused_kernel(const float* __restrict__ x, float* __restrict__ out, int rows) {
    int bid  = blockIdx.x;
    int cb   = bid & 1;                 // column block: 0 or 1
    int p    = bid >> 1;                // row chunk 0..P-1
    int col4 = cb * 256 + threadIdx.x;  // 0..NF4-1
    int rpc  = rows / P;                // 32 for rows=8192
    int r0   = p * rpc;

    const float4* xp = reinterpret_cast<const float4*>(x);

    // ---------------- Phase 1: column reduce (MLP=8) ----------------
    float sx = 0.f, sy = 0.f, sz = 0.f, sw = 0.f;
    float qx = 0.f, qy = 0.f, qz = 0.f, qw = 0.f;

    #pragma unroll 1
    for (int r = 0; r + 8 <= rpc; r += 8) {
        size_t base = (size_t)(r0 + r) * NF4 + col4;
        float4 v0 = xp[base];
        float4 v1 = xp[base + 1 * NF4];
        float4 v2 = xp[base + 2 * NF4];
        float4 v3 = xp[base + 3 * NF4];
        float4 v4 = xp[base + 4 * NF4];
        float4 v5 = xp[base + 5 * NF4];
        float4 v6 = xp[base + 6 * NF4];
        float4 v7 = xp[base + 7 * NF4];
        sx += v0.x; sy += v0.y; sz += v0.z; sw += v0.w;
        qx += v0.x*v0.x; qy += v0.y*v0.y; qz += v0.z*v0.z; qw += v0.w*v0.w;
        sx += v1.x; sy += v1.y; sz += v1.z; sw += v1.w;
        qx += v1.x*v1.x; qy += v1.y*v1.y; qz += v1.z*v1.z; qw += v1.w*v1.w;
        sx += v2.x; sy += v2.y; sz += v2.z; sw += v2.w;
        qx += v2.x*v2.x; qy += v2.y*v2.y; qz += v2.z*v2.z; qw += v2.w*v2.w;
        sx += v3.x; sy += v3.y; sz += v3.z; sw += v3.w;
        qx += v3.x*v3.x; qy += v3.y*v3.y; qz += v3.z*v3.z; qw += v3.w*v3.w;
        sx += v4.x; sy += v4.y; sz += v4.z; sw += v4.w;
        qx += v4.x*v4.x; qy += v4.y*v4.y; qz += v4.z*v4.z; qw += v4.w*v4.w;
        sx += v5.x; sy += v5.y; sz += v5.z; sw += v5.w;
        qx += v5.x*v5.x; qy += v5.y*v5.y; qz += v5.z*v5.z; qw += v5.w*v5.w;
        sx += v6.x; sy += v6.y; sz += v6.z; sw += v6.w;
        qx += v6.x*v6.x; qy += v6.y*v6.y; qz += v6.z*v6.z; qw += v6.w*v6.w;
        sx += v7.x; sy += v7.y; sz += v7.z; sw += v7.w;
        qx += v7.x*v7.x; qy += v7.y*v7.y; qz += v7.z*v7.z; qw += v7.w*v7.w;
    }
    // tail (none for rows=8192)
    for (int r = (rpc & ~7); r < rpc; ++r) {
        float4 v = xp[(size_t)(r0 + r) * NF4 + col4];
        sx += v.x; sy += v.y; sz += v.z; sw += v.w;
        qx += v.x*v.x; qy += v.y*v.y; qz += v.z*v.z; qw += v.w*v.w;
    }

    {
        size_t o = (size_t)p * NF4 + col4;
        reinterpret_cast<float4*>(g_ps)[o] = make_float4(sx, sy, sz, sw);
        reinterpret_cast<float4*>(g_pq)[o] = make_float4(qx, qy, qz, qw);
    }

    grid_barrier(&g_bar1);

    // ---------------- Phase 2: stats. CTA bid owns col4 group == bid ------
    {
        __shared__ float4 s_s[8];
        __shared__ float4 s_q[8];
        int t = threadIdx.x;                 // one partial per thread (P=256)
        float4 a = reinterpret_cast<const float4*>(g_ps)[(size_t)t * NF4 + bid];
        float4 b = reinterpret_cast<const float4*>(g_pq)[(size_t)t * NF4 + bid];
        #pragma unroll
        for (int off = 16; off > 0; off >>= 1) {
            a.x += __shfl_xor_sync(0xffffffffu, a.x, off);
            a.y += __shfl_xor_sync(0xffffffffu, a.y, off);
            a.z += __shfl_xor_sync(0xffffffffu, a.z, off);
            a.w += __shfl_xor_sync(0xffffffffu, a.w, off);
            b.x += __shfl_xor_sync(0xffffffffu, b.x, off);
            b.y += __shfl_xor_sync(0xffffffffu, b.y, off);
            b.z += __shfl_xor_sync(0xffffffffu, b.z, off);
            b.w += __shfl_xor_sync(0xffffffffu, b.w, off);
        }
        int warp = t >> 5, lane = t & 31;
        if (lane == 0) { s_s[warp] = a; s_q[warp] = b; }
        __syncthreads();
        if (warp == 0 && lane < 8) {
            a = s_s[lane]; b = s_q[lane];
            #pragma unroll
            for (int off = 4; off > 0; off >>= 1) {
                a.x += __shfl_xor_sync(0xffu, a.x, off);
                a.y += __shfl_xor_sync(0xffu, a.y, off);
                a.z += __shfl_xor_sync(0xffu, a.z, off);
                a.w += __shfl_xor_sync(0xffu, a.w, off);
                b.x += __shfl_xor_sync(0xffu, b.x, off);
                b.y += __shfl_xor_sync(0xffu, b.y, off);
                b.z += __shfl_xor_sync(0xffu, b.z, off);
                b.w += __shfl_xor_sync(0xffu, b.w, off);
            }
            if (lane == 0) {
                float n = (float)rows;
                float inv_n = 1.0f / n;
                float inv_n1 = 1.0f / (n - 1.0f);
                float4 m, is;
                m.x = a.x * inv_n; m.y = a.y * inv_n;
                m.z = a.z * inv_n; m.w = a.w * inv_n;
                is.x = rsqrtf((b.x - n * m.x * m.x) * inv_n1 + EPS);
                is.y = rsqrtf((b.y - n * m.y * m.y) * inv_n1 + EPS);
                is.z = rsqrtf((b.z - n * m.z * m.z) * inv_n1 + EPS);
                is.w = rsqrtf((b.w - n * m.w * m.w) * inv_n1 + EPS);
                reinterpret_cast<float4*>(g_mean)[bid] = m;
                reinterpret_cast<float4*>(g_istd)[bid] = is;
            }
        }
    }

    grid_barrier(&g_bar2);

    // ---------------- Phase 3: normalize own tile (reads mostly L2/L1) ----
    {
        float4 m = reinterpret_cast<const float4*>(g_mean)[col4];
        float4 s = reinterpret_cast<const float4*>(g_istd)[col4];
        float4* op = reinterpret_cast<float4*>(out);

        #pragma unroll 1
        for (int r = 0; r + 4 <= rpc; r += 4) {
            size_t base = (size_t)(r0 + r) * NF4 + col4;
            float4 v0 = xp[base];
            float4 v1 = xp[base + 1 * NF4];
            float4 v2 = xp[base + 2 * NF4];
            float4 v3 = xp[base + 3 * NF4];
            float4 o0, o1, o2, o3;
            o0.x = (v0.x - m.x) * s.x; o0.y = (v0.y - m.y) * s.y;
            o0.z = (v0.z - m.z) * s.z; o0.w = (v0.w - m.w) * s.w;
            o1.x = (v1.x - m.x) * s.x; o1.y = (v1.y - m.y) * s.y;
            o1.z = (v1.z - m.z) * s.z; o1.w = (v1.w - m.w) * s.w;
            o2.x = (v2.x - m.x) * s.x; o2.y = (v2.y - m.y) * s.y;
            o2.z = (v2.z - m.z) * s.z; o2.w = (v2.w - m.w) * s.w;
            o3.x = (v3.x - m.x) * s.x; o3.y = (v3.y - m.y) * s.y;
            o3.z = (v3.z - m.z) * s.z; o3.w = (v3.w - m.w) * s.w;
            op[base]           = o0;
            op[base + 1 * NF4] = o1;
            op[base + 2 * NF4] = o2;
            op[base + 3 * NF4] = o3;
        }
        for (int r = (rpc & ~3); r < rpc; ++r) {
            size_t i = (size_t)(r0 + r) * NF4 + col4;
            float4 v = xp[i];
            float4 o;
            o.x = (v.x - m.x) * s.x; o.y = (v.y - m.y) * s.y;
            o.z = (v.z - m.z) * s.z; o.w = (v.w - m.w) * s.w;
            op[i] = o;
        }
    }

    // ---------------- Reset barriers for next graph replay ----------------
    __syncthreads();
    if (threadIdx.x == 0) {
        unsigned prev = atomicAdd(&g_bar3, 1u);
        if (prev == GRID - 1) {
            g_bar1 = 0;
            g_bar2 = 0;
            g_bar3 = 0;
        }
    }
}

extern "C" void kernel_launch(void* const* d_in, const int* in_sizes, int n_in,
                              void* d_out, int out_size) {
    const float* x = (const float*)d_in[0];
    float* out = (float*)d_out;
    int rows = in_sizes[0] / NF;     // 8192

    fused_kernel<<<GRID, 256>>>(x, out, rows);
}

// round 6
// speedup vs baseline: 1.1693x; 1.0236x over previous
#include <cuda_runtime.h>
#include <cuda_bf16.h>

#define NF    2048
#define NF4   (NF / 4)       // 512 float4 per row
#define P     296            // row chunks == GRID/2
#define GRID  592            // 148 SMs x 4 CTAs, exactly balanced
#define EPS   1e-6f

// Scratch (__device__ globals per allocation-free rule)
__device__ __align__(16) float g_ps[P * NF];   // partial sums   [p][c]
__device__ __align__(16) float g_pq[P * NF];   // partial sumsq  [p][c]
__device__ __align__(16) float g_mean[NF];
__device__ __align__(16) float g_istd[NF];

// Grid-barrier counters (zero-init; last CTA resets for graph replays)
__device__ volatile unsigned g_bar1;
__device__ volatile unsigned g_bar2;
__device__ unsigned g_bar3;

__device__ __forceinline__ void grid_barrier(volatile unsigned* bar) {
    __syncthreads();
    __threadfence();
    if (threadIdx.x == 0) {
        atomicAdd((unsigned*)bar, 1u);
        while (*bar < GRID) { __nanosleep(32); }
    }
    __syncthreads();
    __threadfence();
}

__global__ void __launch_bounds__(256, 4)
fused_kernel(const float* __restrict__ x, float* __restrict__ out, int rows) {
    int bid  = blockIdx.x;
    int cb   = bid & 1;                 // column block: 0 or 1
    int p    = bid >> 1;                // row chunk 0..P-1
    int col4 = cb * 256 + threadIdx.x;  // 0..NF4-1
    int r0   = (int)(((long long)p * rows) / P);
    int r1   = (int)(((long long)(p + 1) * rows) / P);

    const float4* xp = reinterpret_cast<const float4*>(x);

    // ---------------- Phase 1: column reduce (MLP=8) ----------------
    float sx = 0.f, sy = 0.f, sz = 0.f, sw = 0.f;
    float qx = 0.f, qy = 0.f, qz = 0.f, qw = 0.f;

    int r = r0;
    #pragma unroll 1
    for (; r + 8 <= r1; r += 8) {
        size_t base = (size_t)r * NF4 + col4;
        float4 v0 = xp[base];
        float4 v1 = xp[base + 1 * NF4];
        float4 v2 = xp[base + 2 * NF4];
        float4 v3 = xp[base + 3 * NF4];
        float4 v4 = xp[base + 4 * NF4];
        float4 v5 = xp[base + 5 * NF4];
        float4 v6 = xp[base + 6 * NF4];
        float4 v7 = xp[base + 7 * NF4];
        sx += v0.x; sy += v0.y; sz += v0.z; sw += v0.w;
        qx += v0.x*v0.x; qy += v0.y*v0.y; qz += v0.z*v0.z; qw += v0.w*v0.w;
        sx += v1.x; sy += v1.y; sz += v1.z; sw += v1.w;
        qx += v1.x*v1.x; qy += v1.y*v1.y; qz += v1.z*v1.z; qw += v1.w*v1.w;
        sx += v2.x; sy += v2.y; sz += v2.z; sw += v2.w;
        qx += v2.x*v2.x; qy += v2.y*v2.y; qz += v2.z*v2.z; qw += v2.w*v2.w;
        sx += v3.x; sy += v3.y; sz += v3.z; sw += v3.w;
        qx += v3.x*v3.x; qy += v3.y*v3.y; qz += v3.z*v3.z; qw += v3.w*v3.w;
        sx += v4.x; sy += v4.y; sz += v4.z; sw += v4.w;
        qx += v4.x*v4.x; qy += v4.y*v4.y; qz += v4.z*v4.z; qw += v4.w*v4.w;
        sx += v5.x; sy += v5.y; sz += v5.z; sw += v5.w;
        qx += v5.x*v5.x; qy += v5.y*v5.y; qz += v5.z*v5.z; qw += v5.w*v5.w;
        sx += v6.x; sy += v6.y; sz += v6.z; sw += v6.w;
        qx += v6.x*v6.x; qy += v6.y*v6.y; qz += v6.z*v6.z; qw += v6.w*v6.w;
        sx += v7.x; sy += v7.y; sz += v7.z; sw += v7.w;
        qx += v7.x*v7.x; qy += v7.y*v7.y; qz += v7.z*v7.z; qw += v7.w*v7.w;
    }
    #pragma unroll 1
    for (; r < r1; ++r) {
        float4 v = xp[(size_t)r * NF4 + col4];
        sx += v.x; sy += v.y; sz += v.z; sw += v.w;
        qx += v.x*v.x; qy += v.y*v.y; qz += v.z*v.z; qw += v.w*v.w;
    }

    {
        size_t o = (size_t)p * NF4 + col4;
        reinterpret_cast<float4*>(g_ps)[o] = make_float4(sx, sy, sz, sw);
        reinterpret_cast<float4*>(g_pq)[o] = make_float4(qx, qy, qz, qw);
    }

    grid_barrier(&g_bar1);

    // ------- Phase 2: stats. CTAs 0..511 each own col4 group == bid -------
    if (bid < NF4) {
        __shared__ float4 s_s[8];
        __shared__ float4 s_q[8];
        int t = threadIdx.x;
        // P=296 partials: thread t sums entries t and t+256 (if < P)
        float4 a = reinterpret_cast<const float4*>(g_ps)[(size_t)t * NF4 + bid];
        float4 b = reinterpret_cast<const float4*>(g_pq)[(size_t)t * NF4 + bid];
        if (t + 256 < P) {
            float4 a2 = reinterpret_cast<const float4*>(g_ps)[(size_t)(t + 256) * NF4 + bid];
            float4 b2 = reinterpret_cast<const float4*>(g_pq)[(size_t)(t + 256) * NF4 + bid];
            a.x += a2.x; a.y += a2.y; a.z += a2.z; a.w += a2.w;
            b.x += b2.x; b.y += b2.y; b.z += b2.z; b.w += b2.w;
        }
        #pragma unroll
        for (int off = 16; off > 0; off >>= 1) {
            a.x += __shfl_xor_sync(0xffffffffu, a.x, off);
            a.y += __shfl_xor_sync(0xffffffffu, a.y, off);
            a.z += __shfl_xor_sync(0xffffffffu, a.z, off);
            a.w += __shfl_xor_sync(0xffffffffu, a.w, off);
            b.x += __shfl_xor_sync(0xffffffffu, b.x, off);
            b.y += __shfl_xor_sync(0xffffffffu, b.y, off);
            b.z += __shfl_xor_sync(0xffffffffu, b.z, off);
            b.w += __shfl_xor_sync(0xffffffffu, b.w, off);
        }
        int warp = t >> 5, lane = t & 31;
        if (lane == 0) { s_s[warp] = a; s_q[warp] = b; }
        __syncthreads();
        if (warp == 0 && lane < 8) {
            a = s_s[lane]; b = s_q[lane];
            #pragma unroll
            for (int off = 4; off > 0; off >>= 1) {
                a.x += __shfl_xor_sync(0xffu, a.x, off);
                a.y += __shfl_xor_sync(0xffu, a.y, off);
                a.z += __shfl_xor_sync(0xffu, a.z, off);
                a.w += __shfl_xor_sync(0xffu, a.w, off);
                b.x += __shfl_xor_sync(0xffu, b.x, off);
                b.y += __shfl_xor_sync(0xffu, b.y, off);
                b.z += __shfl_xor_sync(0xffu, b.z, off);
                b.w += __shfl_xor_sync(0xffu, b.w, off);
            }
            if (lane == 0) {
                float n = (float)rows;
                float inv_n = 1.0f / n;
                float inv_n1 = 1.0f / (n - 1.0f);
                float4 m, is;
                m.x = a.x * inv_n; m.y = a.y * inv_n;
                m.z = a.z * inv_n; m.w = a.w * inv_n;
                is.x = rsqrtf((b.x - n * m.x * m.x) * inv_n1 + EPS);
                is.y = rsqrtf((b.y - n * m.y * m.y) * inv_n1 + EPS);
                is.z = rsqrtf((b.z - n * m.z * m.z) * inv_n1 + EPS);
                is.w = rsqrtf((b.w - n * m.w * m.w) * inv_n1 + EPS);
                reinterpret_cast<float4*>(g_mean)[bid] = m;
                reinterpret_cast<float4*>(g_istd)[bid] = is;
            }
        }
    } else {
        __syncthreads();   // keep barrier arrival shape uniform
    }

    grid_barrier(&g_bar2);

    // ---- Phase 3: normalize own tile (x reads hit L2; streaming stores) ----
    {
        float4 m = reinterpret_cast<const float4*>(g_mean)[col4];
        float4 s = reinterpret_cast<const float4*>(g_istd)[col4];
        float4* op = reinterpret_cast<float4*>(out);

        int rr = r0;
        #pragma unroll 1
        for (; rr + 4 <= r1; rr += 4) {
            size_t base = (size_t)rr * NF4 + col4;
            float4 v0 = xp[base];
            float4 v1 = xp[base + 1 * NF4];
            float4 v2 = xp[base + 2 * NF4];
            float4 v3 = xp[base + 3 * NF4];
            float4 o0, o1, o2, o3;
            o0.x = (v0.x - m.x) * s.x; o0.y = (v0.y - m.y) * s.y;
            o0.z = (v0.z - m.z) * s.z; o0.w = (v0.w - m.w) * s.w;
            o1.x = (v1.x - m.x) * s.x; o1.y = (v1.y - m.y) * s.y;
            o1.z = (v1.z - m.z) * s.z; o1.w = (v1.w - m.w) * s.w;
            o2.x = (v2.x - m.x) * s.x; o2.y = (v2.y - m.y) * s.y;
            o2.z = (v2.z - m.z) * s.z; o2.w = (v2.w - m.w) * s.w;
            o3.x = (v3.x - m.x) * s.x; o3.y = (v3.y - m.y) * s.y;
            o3.z = (v3.z - m.z) * s.z; o3.w = (v3.w - m.w) * s.w;
            __stcs(&op[base],           o0);
            __stcs(&op[base + 1 * NF4], o1);
            __stcs(&op[base + 2 * NF4], o2);
            __stcs(&op[base + 3 * NF4], o3);
        }
        #pragma unroll 1
        for (; rr < r1; ++rr) {
            size_t i = (size_t)rr * NF4 + col4;
            float4 v = xp[i];
            float4 o;
            o.x = (v.x - m.x) * s.x; o.y = (v.y - m.y) * s.y;
            o.z = (v.z - m.z) * s.z; o.w = (v.w - m.w) * s.w;
            __stcs(&op[i], o);
        }
    }

    // ---------------- Reset barriers for next graph replay ----------------
    __syncthreads();
    if (threadIdx.x == 0) {
        unsigned prev = atomicAdd(&g_bar3, 1u);
        if (prev == GRID - 1) {
            g_bar1 = 0;
            g_bar2 = 0;
            g_bar3 = 0;
        }
    }
}

extern "C" void kernel_launch(void* const* d_in, const int* in_sizes, int n_in,
                              void* d_out, int out_size) {
    const float* x = (const float*)d_in[0];
    float* out = (float*)d_out;
    int rows = in_sizes[0] / NF;     // 8192

    fused_kernel<<<GRID, 256>>>(x, out, rows);
}